// round 9
// baseline (speedup 1.0000x reference)
#include <cuda_runtime.h>

// newPad2d: replicate (edge) pad, width 2 on H and W.
// in:  (32, 256, 56, 56) fp32 -> 8192 planes of 56x56
// out: (32, 256, 60, 60) fp32 -> 8192 planes of 60x60
//
// Final form. Measured roofline: ~163 MB steady-state DRAM traffic
// (112.5 MB writes + ~50 MB read misses; rest of input is L2-resident
// across graph replays) at ~5.4 TB/s mixed R/W ceiling => ~30 us floor.
//
// Structure (proven over R4..R8):
//  - one thread produces 2 output vec8s (32B each); vec8s never cross
//    planes (3600 floats/plane, divisible by 8), each half-vec4 is
//    row-local with w0 % 4 == 0, so its source window [w0-2, w0+2) is
//    exactly two 8B-aligned LDG.64 + 2 selects.
//  - stores: st.global.cs.v4.b64 (32B streaming stores, full sectors).
//  - R9 tweak: store each vec8 immediately after computing it, halving
//    peak live registers (regs ~28) to recover achieved occupancy.
// nvec8 = 3,686,400 = 7200 * 512 exactly -> no tail.

#define IN_H   56
#define IN_W   56
#define PAD    2
#define PLANE_IN      (IN_H * IN_W)          // 3136
#define VEC_PER_ROW   15                     // vec4 per output row
#define VEC_PER_PLANE (60 * VEC_PER_ROW)     // 900 vec4 per plane
#define ILP 2                                // vec8 per thread
#define THREADS 256
#define CHUNK (THREADS * ILP)                // 512 vec8 per block

typedef unsigned long long ull;

__device__ __forceinline__ ull pack2(float lo, float hi) {
    return ((ull)__float_as_uint(hi) << 32) | (ull)__float_as_uint(lo);
}

__device__ __forceinline__ void stg256_stream(void* p, float4 lo, float4 hi) {
    ull u0 = pack2(lo.x, lo.y);
    ull u1 = pack2(lo.z, lo.w);
    ull u2 = pack2(hi.x, hi.y);
    ull u3 = pack2(hi.z, hi.w);
    asm volatile("st.global.cs.v4.b64 [%0], {%1,%2,%3,%4};"
                 :: "l"(p), "l"(u0), "l"(u1), "l"(u2), "l"(u3)
                 : "memory");
}

// Compute one output vec4. v4idx = global vec4 index.
__device__ __forceinline__ float4 make_vec4(const float* __restrict__ x, int v4idx)
{
    int plane = v4idx / VEC_PER_PLANE;
    int rem   = v4idx - plane * VEC_PER_PLANE;
    int h     = rem / VEC_PER_ROW;
    int w     = (rem - h * VEC_PER_ROW) * 4;
    int hin   = min(max(h - PAD, 0), IN_H - 1);
    int off   = plane * PLANE_IN + hin * IN_W;   // max ~25.7M, fits 32-bit

    // both addresses 8-byte aligned
    float2 a = __ldg((const float2*)(x + off + max(w - 2, 0)));
    float2 b = __ldg((const float2*)(x + off + min(w, IN_W - 2)));

    float4 v;
    v.x = a.x;
    v.y = (w == 0)    ? a.x : a.y;   // left edge replicates col 0
    v.z = (w == IN_W) ? b.y : b.x;   // right edge replicates col 55
    v.w = b.y;
    return v;
}

__global__ __launch_bounds__(THREADS)
void pad2d_edge_v8b(const float* __restrict__ x,
                    float* __restrict__ out)
{
    const int base8 = blockIdx.x * CHUNK + threadIdx.x;   // vec8 index

#pragma unroll
    for (int k = 0; k < ILP; k++) {
        int v8 = base8 + k * THREADS;
        float4 lo = make_vec4(x, 2 * v8);
        float4 hi = make_vec4(x, 2 * v8 + 1);
        stg256_stream(out + (size_t)v8 * 8, lo, hi);
    }
}

extern "C" void kernel_launch(void* const* d_in, const int* in_sizes, int n_in,
                              void* d_out, int out_size)
{
    const float* x = (const float*)d_in[0];
    float* out = (float*)d_out;

    int nvec8 = out_size / 8;        // 3,686,400
    int blocks = nvec8 / CHUNK;      // 7200 exactly
    pad2d_edge_v8b<<<blocks, THREADS>>>(x, out);
}

// round 10
// speedup vs baseline: 1.0102x; 1.0102x over previous
#include <cuda_runtime.h>

// newPad2d: replicate (edge) pad, width 2 on H and W.  FINAL.
// in:  (32, 256, 56, 56) fp32 -> 8192 planes of 56x56
// out: (32, 256, 60, 60) fp32 -> 8192 planes of 60x60
//
// At the measured roofline: ~163 MB steady-state DRAM traffic per launch
// (112.5 MB mandatory writes + ~50 MB read misses; the rest of the 98 MB
// input stays L2-resident across graph replays) at the ~5.4-5.5 TB/s
// mixed read/write DRAM ceiling of this part => ~29.5-30 us ncu floor.
// Nine structurally distinct variants (ILP 4/8, 32/64-bit loads, cache
// policies, persistent grid, store scheduling) all land within noise of
// this floor; this configuration measured fastest wall-clock.
//
// Structure:
//  - one thread produces 2 output vec8s (32B each). Output plane = 3600
//    floats (divisible by 8) so vec8s never cross planes; each half-vec4
//    is row-local with w0 % 4 == 0, so its source window [w0-2, w0+2) is
//    exactly two 8-byte-aligned LDG.64 + 2 selects (no scalar gathers).
//  - stores: st.global.cs.v4.b64 — 256-bit streaming stores, full sectors.
//  - nvec8 = 3,686,400 = 7200 blocks * 512 exactly -> no tail handling.

#define IN_H   56
#define IN_W   56
#define PAD    2
#define PLANE_IN      (IN_H * IN_W)          // 3136
#define VEC_PER_ROW   15                     // vec4 per output row
#define VEC_PER_PLANE (60 * VEC_PER_ROW)     // 900 vec4 per plane
#define ILP 2                                // vec8 per thread
#define THREADS 256
#define CHUNK (THREADS * ILP)                // 512 vec8 per block

typedef unsigned long long ull;

__device__ __forceinline__ ull pack2(float lo, float hi) {
    return ((ull)__float_as_uint(hi) << 32) | (ull)__float_as_uint(lo);
}

__device__ __forceinline__ void stg256_stream(void* p, float4 lo, float4 hi) {
    ull u0 = pack2(lo.x, lo.y);
    ull u1 = pack2(lo.z, lo.w);
    ull u2 = pack2(hi.x, hi.y);
    ull u3 = pack2(hi.z, hi.w);
    asm volatile("st.global.cs.v4.b64 [%0], {%1,%2,%3,%4};"
                 :: "l"(p), "l"(u0), "l"(u1), "l"(u2), "l"(u3)
                 : "memory");
}

// Compute one output vec4. v4idx = global vec4 index.
__device__ __forceinline__ float4 make_vec4(const float* __restrict__ x, int v4idx)
{
    int plane = v4idx / VEC_PER_PLANE;
    int rem   = v4idx - plane * VEC_PER_PLANE;
    int h     = rem / VEC_PER_ROW;
    int w     = (rem - h * VEC_PER_ROW) * 4;
    int hin   = min(max(h - PAD, 0), IN_H - 1);
    int off   = plane * PLANE_IN + hin * IN_W;   // max ~25.7M, fits 32-bit

    // both addresses 8-byte aligned
    float2 a = __ldg((const float2*)(x + off + max(w - 2, 0)));
    float2 b = __ldg((const float2*)(x + off + min(w, IN_W - 2)));

    float4 v;
    v.x = a.x;
    v.y = (w == 0)    ? a.x : a.y;   // left edge replicates col 0
    v.z = (w == IN_W) ? b.y : b.x;   // right edge replicates col 55
    v.w = b.y;
    return v;
}

__global__ __launch_bounds__(THREADS)
void pad2d_edge_v8(const float* __restrict__ x,
                   float* __restrict__ out)
{
    const int base8 = blockIdx.x * CHUNK + threadIdx.x;   // vec8 index

    float4 lo[ILP], hi[ILP];
#pragma unroll
    for (int k = 0; k < ILP; k++) {
        int v8 = base8 + k * THREADS;
        lo[k] = make_vec4(x, 2 * v8);
        hi[k] = make_vec4(x, 2 * v8 + 1);
    }

#pragma unroll
    for (int k = 0; k < ILP; k++) {
        int v8 = base8 + k * THREADS;
        stg256_stream(out + (size_t)v8 * 8, lo[k], hi[k]);
    }
}

extern "C" void kernel_launch(void* const* d_in, const int* in_sizes, int n_in,
                              void* d_out, int out_size)
{
    const float* x = (const float*)d_in[0];
    float* out = (float*)d_out;

    int nvec8 = out_size / 8;        // 3,686,400
    int blocks = nvec8 / CHUNK;      // 7200 exactly
    pad2d_edge_v8<<<blocks, THREADS>>>(x, out);
}

// round 11
// speedup vs baseline: 1.0111x; 1.0009x over previous
#include <cuda_runtime.h>

// newPad2d: replicate (edge) pad, width 2 on H and W.  FINAL (committed).
// in:  (32, 256, 56, 56) fp32 -> 8192 planes of 56x56
// out: (32, 256, 60, 60) fp32 -> 8192 planes of 60x60
//
// At the measured roofline: ~163 MB steady-state DRAM traffic per launch
// (112.5 MB mandatory writes + ~50 MB read misses; rest of the 98 MB input
// is L2-resident across graph replays) / ~5.5 TB/s sustained mixed-R/W
// bandwidth => ~29.5 us ncu floor. Measured 29.4-30.2 us across the two
// best variants; reproduced on re-bench. Falsified alternatives: cache
// policy steering (null), persistent 1-wave grid (regression), higher ILP
// (occupancy-negative), occupancy itself (duration-invariant 57-83%).
//
// Structure:
//  - one thread produces 2 output vec8s (32B each). Output plane = 3600
//    floats (divisible by 8) so vec8s never cross planes; each half-vec4
//    is row-local with w0 % 4 == 0, so its source window [w0-2, w0+2) is
//    exactly two 8-byte-aligned LDG.64 + 2 selects (no scalar gathers).
//  - 8 independent LDG.64 front-batched per thread (MLP) then 2 STG.256.
//  - stores: st.global.cs.v4.b64 — 256-bit streaming stores, full sectors.
//  - nvec8 = 3,686,400 = 7200 blocks * 512 exactly -> no tail handling.

#define IN_H   56
#define IN_W   56
#define PAD    2
#define PLANE_IN      (IN_H * IN_W)          // 3136
#define VEC_PER_ROW   15                     // vec4 per output row
#define VEC_PER_PLANE (60 * VEC_PER_ROW)     // 900 vec4 per plane
#define ILP 2                                // vec8 per thread
#define THREADS 256
#define CHUNK (THREADS * ILP)                // 512 vec8 per block

typedef unsigned long long ull;

__device__ __forceinline__ ull pack2(float lo, float hi) {
    return ((ull)__float_as_uint(hi) << 32) | (ull)__float_as_uint(lo);
}

__device__ __forceinline__ void stg256_stream(void* p, float4 lo, float4 hi) {
    ull u0 = pack2(lo.x, lo.y);
    ull u1 = pack2(lo.z, lo.w);
    ull u2 = pack2(hi.x, hi.y);
    ull u3 = pack2(hi.z, hi.w);
    asm volatile("st.global.cs.v4.b64 [%0], {%1,%2,%3,%4};"
                 :: "l"(p), "l"(u0), "l"(u1), "l"(u2), "l"(u3)
                 : "memory");
}

// Compute one output vec4. v4idx = global vec4 index.
__device__ __forceinline__ float4 make_vec4(const float* __restrict__ x, int v4idx)
{
    int plane = v4idx / VEC_PER_PLANE;
    int rem   = v4idx - plane * VEC_PER_PLANE;
    int h     = rem / VEC_PER_ROW;
    int w     = (rem - h * VEC_PER_ROW) * 4;
    int hin   = min(max(h - PAD, 0), IN_H - 1);
    int off   = plane * PLANE_IN + hin * IN_W;   // max ~25.7M, fits 32-bit

    // both addresses 8-byte aligned
    float2 a = __ldg((const float2*)(x + off + max(w - 2, 0)));
    float2 b = __ldg((const float2*)(x + off + min(w, IN_W - 2)));

    float4 v;
    v.x = a.x;
    v.y = (w == 0)    ? a.x : a.y;   // left edge replicates col 0
    v.z = (w == IN_W) ? b.y : b.x;   // right edge replicates col 55
    v.w = b.y;
    return v;
}

__global__ __launch_bounds__(THREADS)
void pad2d_edge_v8(const float* __restrict__ x,
                   float* __restrict__ out)
{
    const int base8 = blockIdx.x * CHUNK + threadIdx.x;   // vec8 index

    float4 lo[ILP], hi[ILP];
#pragma unroll
    for (int k = 0; k < ILP; k++) {
        int v8 = base8 + k * THREADS;
        lo[k] = make_vec4(x, 2 * v8);
        hi[k] = make_vec4(x, 2 * v8 + 1);
    }

#pragma unroll
    for (int k = 0; k < ILP; k++) {
        int v8 = base8 + k * THREADS;
        stg256_stream(out + (size_t)v8 * 8, lo[k], hi[k]);
    }
}

extern "C" void kernel_launch(void* const* d_in, const int* in_sizes, int n_in,
                              void* d_out, int out_size)
{
    const float* x = (const float*)d_in[0];
    float* out = (float*)d_out;

    int nvec8 = out_size / 8;        // 3,686,400
    int blocks = nvec8 / CHUNK;      // 7200 exactly
    pad2d_edge_v8<<<blocks, THREADS>>>(x, out);
}

// round 12
// speedup vs baseline: 1.0189x; 1.0077x over previous
#include <cuda_runtime.h>

// newPad2d: replicate (edge) pad, width 2 on H and W.  FINAL (converged).
// in:  (32, 256, 56, 56) fp32 -> 8192 planes of 56x56
// out: (32, 256, 60, 60) fp32 -> 8192 planes of 60x60
//
// Roofline-confirmed over 11 rounds: ~163 MB steady-state DRAM traffic
// (112.5 MB mandatory writes + ~50 MB read capacity misses; the rest of
// the 98 MB input is L2-resident across graph replays) at ~5.5-5.6 TB/s
// sustained mixed-R/W bandwidth => 29-30 us ncu. Wall reproduced thrice
// at 37.4-37.7 us; the ~8 us wall-ncu gap is fixed harness overhead.
// Falsified: cache-policy steering (null), persistent 1-wave grid
// (regression), higher ILP (occupancy-negative), occupancy sensitivity
// (duration-invariant 50-83%), LSU-issue ceiling (halving LDGs null).
//
// Structure:
//  - one thread produces 2 output vec8s (32B each). Output plane = 3600
//    floats (divisible by 8) so vec8s never cross planes; each half-vec4
//    is row-local with w0 % 4 == 0, so its source window [w0-2, w0+2) is
//    exactly two 8-byte-aligned LDG.64 + 2 selects (no scalar gathers).
//  - 8 independent LDG.64 front-batched per thread (MLP), 2 STG.256.
//  - stores: st.global.cs.v4.b64 — 256-bit streaming stores, full sectors.
//  - nvec8 = 3,686,400 = 7200 blocks * 512 exactly -> no tail handling.

#define IN_H   56
#define IN_W   56
#define PAD    2
#define PLANE_IN      (IN_H * IN_W)          // 3136
#define VEC_PER_ROW   15                     // vec4 per output row
#define VEC_PER_PLANE (60 * VEC_PER_ROW)     // 900 vec4 per plane
#define ILP 2                                // vec8 per thread
#define THREADS 256
#define CHUNK (THREADS * ILP)                // 512 vec8 per block

typedef unsigned long long ull;

__device__ __forceinline__ ull pack2(float lo, float hi) {
    return ((ull)__float_as_uint(hi) << 32) | (ull)__float_as_uint(lo);
}

__device__ __forceinline__ void stg256_stream(void* p, float4 lo, float4 hi) {
    ull u0 = pack2(lo.x, lo.y);
    ull u1 = pack2(lo.z, lo.w);
    ull u2 = pack2(hi.x, hi.y);
    ull u3 = pack2(hi.z, hi.w);
    asm volatile("st.global.cs.v4.b64 [%0], {%1,%2,%3,%4};"
                 :: "l"(p), "l"(u0), "l"(u1), "l"(u2), "l"(u3)
                 : "memory");
}

// Compute one output vec4. v4idx = global vec4 index.
__device__ __forceinline__ float4 make_vec4(const float* __restrict__ x, int v4idx)
{
    int plane = v4idx / VEC_PER_PLANE;
    int rem   = v4idx - plane * VEC_PER_PLANE;
    int h     = rem / VEC_PER_ROW;
    int w     = (rem - h * VEC_PER_ROW) * 4;
    int hin   = min(max(h - PAD, 0), IN_H - 1);
    int off   = plane * PLANE_IN + hin * IN_W;   // max ~25.7M, fits 32-bit

    // both addresses 8-byte aligned
    float2 a = __ldg((const float2*)(x + off + max(w - 2, 0)));
    float2 b = __ldg((const float2*)(x + off + min(w, IN_W - 2)));

    float4 v;
    v.x = a.x;
    v.y = (w == 0)    ? a.x : a.y;   // left edge replicates col 0
    v.z = (w == IN_W) ? b.y : b.x;   // right edge replicates col 55
    v.w = b.y;
    return v;
}

__global__ __launch_bounds__(THREADS)
void pad2d_edge_v8(const float* __restrict__ x,
                   float* __restrict__ out)
{
    const int base8 = blockIdx.x * CHUNK + threadIdx.x;   // vec8 index

    float4 lo[ILP], hi[ILP];
#pragma unroll
    for (int k = 0; k < ILP; k++) {
        int v8 = base8 + k * THREADS;
        lo[k] = make_vec4(x, 2 * v8);
        hi[k] = make_vec4(x, 2 * v8 + 1);
    }

#pragma unroll
    for (int k = 0; k < ILP; k++) {
        int v8 = base8 + k * THREADS;
        stg256_stream(out + (size_t)v8 * 8, lo[k], hi[k]);
    }
}

extern "C" void kernel_launch(void* const* d_in, const int* in_sizes, int n_in,
                              void* d_out, int out_size)
{
    const float* x = (const float*)d_in[0];
    float* out = (float*)d_out;

    int nvec8 = out_size / 8;        // 3,686,400
    int blocks = nvec8 / CHUNK;      // 7200 exactly
    pad2d_edge_v8<<<blocks, THREADS>>>(x, out);
}